// round 12
// baseline (speedup 1.0000x reference)
#include <cuda_runtime.h>
#include <cuda_bf16.h>
#include <math.h>
#include <stdint.h>

#define BB 4
#define SEQ 4096
#define DM 1024
#define K2 2048                 // stored [hi|lo] concatenated K
#define KB2 (K2*2)              // bytes per row (4096)
#define KCH 256
#define ROWS (BB*SEQ)           // 16384
#define NPROJ (6*KCH)           // 1536
#define CHUNK 2048
#define NKIT3 48                // 3-term virtual k-tiles (64 elems each)

// GEMM tiling: 128(M) x 128(N), k-tile 64, 3-stage cp.async pipeline, 2 CTA/SM
#define TM 128
#define TN 128
#define STAGE_BYTES 32768       // A 16KB + B 16KB
#define NSTAGE 3
#define GSMEM (NSTAGE*STAGE_BYTES)   // 96 KB

// ---------------- scratch (global device memory, allocation-free) ----------
__device__ __align__(16) float g_proj [(size_t)ROWS*NPROJ];
__device__ __align__(16) float g_pq   [(size_t)ROWS*KCH];
__device__ __align__(16) float g_alpha[(size_t)BB*KCH*SEQ];
__device__ __align__(16) float g_dr   [(size_t)BB*KCH*SEQ];
__device__ __align__(16) float g_di   [(size_t)BB*KCH*SEQ];
__device__ __align__(16) float g_cosb [(size_t)ROWS*KCH];
__device__ __align__(16) float g_sinb [(size_t)ROWS*KCH];
__device__ __align__(16) float g_betab[(size_t)ROWS*KCH];
__device__ __align__(16) float g_gb   [(size_t)ROWS*KCH];
__device__ __align__(16) float g_rr   [(size_t)ROWS*KCH];
__device__ __align__(16) float g_ri   [(size_t)ROWS*KCH];

// bf16 [hi|lo] operands (3-term pattern realized by k-tile remap at staging)
__device__ __align__(16) __nv_bfloat16 g_xcat  [(size_t)ROWS*K2];
__device__ __align__(16) __nv_bfloat16 g_wpcat [(size_t)NPROJ*K2];
__device__ __align__(16) __nv_bfloat16 g_wqcat [(size_t)KCH*K2];
__device__ __align__(16) __nv_bfloat16 g_wrcat [(size_t)DM*K2];
__device__ __align__(16) __nv_bfloat16 g_rhocat[(size_t)ROWS*K2];

// ---------------- helpers --------------------------------------------------
__device__ __forceinline__ uint32_t smem_u32(const void* p) {
    uint32_t a;
    asm("{ .reg .u64 t; cvta.to.shared.u64 t, %1; cvt.u32.u64 %0, t; }" : "=r"(a) : "l"(p));
    return a;
}
__device__ __forceinline__ void cp16(uint32_t s, const void* g) {
    asm volatile("cp.async.cg.shared.global [%0], [%1], 16;" :: "r"(s), "l"(g) : "memory");
}
#define CP_COMMIT() asm volatile("cp.async.commit_group;" ::: "memory")

__device__ __forceinline__ void ldsm4(uint32_t* r, uint32_t addr) {
    asm volatile("ldmatrix.sync.aligned.m8n8.x4.shared.b16 {%0,%1,%2,%3}, [%4];"
                 : "=r"(r[0]), "=r"(r[1]), "=r"(r[2]), "=r"(r[3]) : "r"(addr));
}
__device__ __forceinline__ void mma16816(float* c, const uint32_t* a, const uint32_t* b) {
    asm volatile("mma.sync.aligned.m16n8k16.row.col.f32.bf16.bf16.f32 "
                 "{%0,%1,%2,%3}, {%4,%5,%6,%7}, {%8,%9}, {%0,%1,%2,%3};"
                 : "+f"(c[0]), "+f"(c[1]), "+f"(c[2]), "+f"(c[3])
                 : "r"(a[0]), "r"(a[1]), "r"(a[2]), "r"(a[3]), "r"(b[0]), "r"(b[1]));
}
__device__ __forceinline__ float sigm(float x) { return 1.0f / (1.0f + expf(-x)); }
__device__ __forceinline__ float softplusf(float x) { return (x > 20.0f) ? x : log1pf(expf(x)); }
__device__ __forceinline__ void bsplit(float v, __nv_bfloat16& h, __nv_bfloat16& l) {
    h = __float2bfloat16(v);
    l = __float2bfloat16(v - __bfloat162float(h));
}

// ---------------- split fp32 (rows x 1024) -> bf16 [hi|lo] (rows x 2048) ----
__global__ void split_cat_kernel(const float4* __restrict__ src, int n4, int which) {
    int i = blockIdx.x * 256 + threadIdx.x;
    if (i >= n4) return;
    float4 v = src[i];
    __nv_bfloat16* dst = (which == 0) ? g_xcat : ((which == 1) ? g_wpcat : g_wqcat);
    int row = i >> 8, q = i & 255;
    size_t base = (size_t)row * K2 + q * 4;
    __nv_bfloat16 h[4], l[4];
    bsplit(v.x, h[0], l[0]); bsplit(v.y, h[1], l[1]);
    bsplit(v.z, h[2], l[2]); bsplit(v.w, h[3], l[3]);
#pragma unroll
    for (int j = 0; j < 4; j++) {
        dst[base + j]        = h[j];
        dst[base + 1024 + j] = l[j];
    }
}

// W_res (1024 x 1022) -> padded [hi|lo]
__global__ void wres_split_cat_kernel(const float* __restrict__ W) {
    int i = blockIdx.x * 256 + threadIdx.x;       // 0 .. 1024*1024-1
    int d = i >> 10, j = i & 1023;
    float v = (j < 1022) ? W[(size_t)d * 1022 + j] : 0.0f;
    __nv_bfloat16 h, l; bsplit(v, h, l);
    size_t base = (size_t)d * K2;
    g_wrcat[base + j]        = h;
    g_wrcat[base + 1024 + j] = l;
}

// ---------------- stage one 64-wide k-tile (A 128 rows, B 128 rows) --------
__device__ __forceinline__ void stage_tile(
    uint32_t sbase, const char* gA, const char* gB,
    uint32_t srow, uint32_t sseg, size_t aOff, size_t bOff)
{
    uint32_t sw = (sseg ^ (srow & 7)) * 16;
#pragma unroll
    for (int r = 0; r < 4; r++) {
        uint32_t row = srow + r * 32;
        cp16(sbase + row * 128 + sw, gA + aOff + (size_t)row * KB2 + sseg * 16);
    }
#pragma unroll
    for (int r = 0; r < 4; r++) {
        uint32_t row = srow + r * 32;
        cp16(sbase + 16384 + row * 128 + sw, gB + bOff + (size_t)row * KB2 + sseg * 16);
    }
}

// virtual k-tile -> stored k-tile: A pattern [hi|hi|lo], B pattern [hi|lo|hi]
__device__ __forceinline__ int amap(int kt) { return (kt < 16) ? kt : kt - 16; }
__device__ __forceinline__ int bmap(int kt) { return (kt < 32) ? kt : kt - 32; }

// ---------------- HMMA GEMM: C[m,n] = sc * sum_k A[m,k]B[n,k] (+bias[n]) ----
// mode 0: A=g_xcat, B=g_wpcat, C=g_proj (3-term, 48 tiles)
// mode 1: A=g_xcat, B=g_wqcat, C=g_pq   (single-term, 16 tiles)
// mode 2: A=g_rhocat, B=g_wrcat, C=ext  (3-term, 48 tiles)
__global__ __launch_bounds__(256, 2) void mma_gemm(
    const float* __restrict__ bias, const float* __restrict__ scale_ptr,
    float* __restrict__ C_ext, int Nt, int nkit, int mode)
{
    extern __shared__ char smem[];
    const __nv_bfloat16 *A, *B; float* C;
    if (mode == 2)      { A = g_rhocat; B = g_wrcat; C = C_ext;  }
    else if (mode == 0) { A = g_xcat;   B = g_wpcat; C = g_proj; }
    else                { A = g_xcat;   B = g_wqcat; C = g_pq;   }

    uint32_t sb = smem_u32(smem);
    int tid = threadIdx.x, lane = tid & 31, wid = tid >> 5;
    int wm = wid >> 2, wn = wid & 3;               // warps 2(m) x 4(n), warp tile 64x32
    int m0 = blockIdx.y * TM, n0 = blockIdx.x * TN;

    const char* gA = (const char*)A + (size_t)m0 * KB2;
    const char* gB = (const char*)B + (size_t)n0 * KB2;

    uint32_t srow = (uint32_t)(tid >> 3), sseg = (uint32_t)(tid & 7);

    // ldmatrix lane geometry
    int rowA = wm * 64 + (lane & 15);
    int segA = lane >> 4;
    int xorA = rowA & 7;
    int rowBin = (lane & 7) + ((lane >> 4) << 3);
    int segB = (lane >> 3) & 1;

    float acc[4][4][4];
#pragma unroll
    for (int mi = 0; mi < 4; mi++)
#pragma unroll
        for (int nj = 0; nj < 4; nj++)
#pragma unroll
            for (int q = 0; q < 4; q++) acc[mi][nj][q] = 0.0f;

    // prologue: stage k-tiles 0..1
#pragma unroll
    for (int s = 0; s < NSTAGE - 1; s++) {
        if (s < nkit)
            stage_tile(sb + s * STAGE_BYTES, gA, gB, srow, sseg,
                       (size_t)amap(s) * 128, (size_t)bmap(s) * 128);
        CP_COMMIT();
    }

    int buf = 0;
    for (int kt = 0; kt < nkit; kt++) {
        asm volatile("cp.async.wait_group 1;" ::: "memory");
        __syncthreads();
        if (kt + 2 < nkit) {
            int pb = buf + 2; if (pb >= NSTAGE) pb -= NSTAGE;
            stage_tile(sb + pb * STAGE_BYTES, gA, gB, srow, sseg,
                       (size_t)amap(kt + 2) * 128, (size_t)bmap(kt + 2) * 128);
        }
        CP_COMMIT();

        uint32_t bufA = sb + buf * STAGE_BYTES;
        uint32_t bufB = bufA + 16384;
#pragma unroll
        for (int ks = 0; ks < 4; ks++) {
            uint32_t a[4][4], b[2][4];
#pragma unroll
            for (int mi = 0; mi < 4; mi++) {
                uint32_t addr = bufA + (uint32_t)(rowA + mi * 16) * 128
                              + (uint32_t)(((ks * 2 + segA) ^ xorA) * 16);
                ldsm4(a[mi], addr);
            }
#pragma unroll
            for (int j2 = 0; j2 < 2; j2++) {
                int rb = wn * 32 + j2 * 16 + rowBin;
                uint32_t addr = bufB + (uint32_t)rb * 128
                              + (uint32_t)(((ks * 2 + segB) ^ (rb & 7)) * 16);
                ldsm4(b[j2], addr);
            }
#pragma unroll
            for (int mi = 0; mi < 4; mi++) {
#pragma unroll
                for (int j2 = 0; j2 < 2; j2++) {
                    mma16816(acc[mi][j2 * 2],     a[mi], &b[j2][0]);
                    mma16816(acc[mi][j2 * 2 + 1], a[mi], &b[j2][2]);
                }
            }
        }
        if (++buf == NSTAGE) buf = 0;
    }

    // epilogue
    float sc = scale_ptr ? *scale_ptr : 1.0f;
#pragma unroll
    for (int mi = 0; mi < 4; mi++) {
#pragma unroll
        for (int nj = 0; nj < 4; nj++) {
            int row = m0 + wm * 64 + mi * 16 + (lane >> 2);
            int col = n0 + wn * 32 + nj * 8 + (lane & 3) * 2;
            float b0 = 0.0f, b1 = 0.0f;
            if (bias) { b0 = bias[col]; b1 = bias[col + 1]; }
            float2 v0 = make_float2(acc[mi][nj][0] * sc + b0, acc[mi][nj][1] * sc + b1);
            float2 v1 = make_float2(acc[mi][nj][2] * sc + b0, acc[mi][nj][3] * sc + b1);
            *(float2*)(C + (size_t)row * Nt + col)       = v0;
            *(float2*)(C + (size_t)(row + 8) * Nt + col) = v1;
        }
    }
}

// ---------------- prescan: activations + transpose for the scan -----------
__global__ __launch_bounds__(256) void prescan_kernel() {
    __shared__ float t_a [32][33];
    __shared__ float t_dr[32][33];
    __shared__ float t_di[32][33];

    int bk = blockIdx.x;
    int kb = bk & 7, nb = (bk >> 3) & 127, b = bk >> 10;
    int k0 = kb * 32, n0 = nb * 32;
    int tx = threadIdx.x & 31;
    int ty = threadIdx.x >> 5;

#pragma unroll
    for (int nn = 0; nn < 4; nn++) {
        int nl = nn * 8 + ty;
        int n = n0 + nl;
        size_t row = (size_t)(b * SEQ + n);
        size_t pb = row * NPROJ + k0 + tx;
        float pa  = g_proj[pb];
        float pw  = g_proj[pb + KCH];
        float pp  = g_proj[pb + 2 * KCH];
        float pal = g_proj[pb + 3 * KCH];
        float pg  = g_proj[pb + 4 * KCH];
        float pbe = g_proj[pb + 5 * KCH];

        float Aamp  = 3.0f * sigm(pa);
        float omega = softplusf(pw);
        float alpha = sigm(pal);
        float gg    = sigm(pg);
        float bee   = sigm(pbe);
        float pos   = log1pf((float)n);
        float angle = fmaf(omega, pos, pp);
        float sn, cs;
        sincosf(angle, &sn, &cs);

        size_t ob = row * KCH + k0 + tx;
        g_cosb[ob] = cs; g_sinb[ob] = sn; g_betab[ob] = bee; g_gb[ob] = gg;

        float oma = 1.0f - alpha;
        t_a [nl][tx] = alpha;
        t_dr[nl][tx] = oma * Aamp * cs;
        t_di[nl][tx] = oma * Aamp * sn;
    }
    __syncthreads();
#pragma unroll
    for (int nn = 0; nn < 4; nn++) {
        int kl = nn * 8 + ty;
        size_t ob = ((size_t)(b * KCH + k0 + kl)) * SEQ + n0 + tx;
        g_alpha[ob] = t_a [tx][kl];
        g_dr   [ob] = t_dr[tx][kl];
        g_di   [ob] = t_di[tx][kl];
    }
}

// ---------------- scan ------------------------------------------------------
__global__ __launch_bounds__(256) void scan_kernel() {
    __shared__ float s_a[CHUNK], s_br[CHUNK], s_bi[CHUNK];
    __shared__ float sc_a[256], sc_r[256], sc_i[256];

    int bk = blockIdx.x;
    int b = bk >> 8, k = bk & 255;
    size_t base = (size_t)bk * SEQ;
    int tid = threadIdx.x;
    float carry_r = 0.0f, carry_i = 0.0f;

    for (int c = 0; c < SEQ / CHUNK; c++) {
        for (int idx = tid; idx < CHUNK; idx += 256) {
            s_a [idx] = g_alpha[base + c * CHUNK + idx];
            s_br[idx] = g_dr   [base + c * CHUNK + idx];
            s_bi[idx] = g_di   [base + c * CHUNK + idx];
        }
        __syncthreads();

        int j0 = tid * 8;
        float Asg = 1.0f, Br = 0.0f, Bi = 0.0f;
#pragma unroll
        for (int j = 0; j < 8; j++) {
            float a = s_a[j0 + j];
            Asg *= a;
            Br = fmaf(a, Br, s_br[j0 + j]);
            Bi = fmaf(a, Bi, s_bi[j0 + j]);
        }
        sc_a[tid] = Asg; sc_r[tid] = Br; sc_i[tid] = Bi;
        __syncthreads();

        for (int off = 1; off < 256; off <<= 1) {
            float pa = 1.0f, pr = 0.0f, pi = 0.0f;
            if (tid >= off) { pa = sc_a[tid - off]; pr = sc_r[tid - off]; pi = sc_i[tid - off]; }
            float ca = sc_a[tid], cr = sc_r[tid], ci = sc_i[tid];
            __syncthreads();
            sc_a[tid] = pa * ca;
            sc_r[tid] = fmaf(ca, pr, cr);
            sc_i[tid] = fmaf(ca, pi, ci);
            __syncthreads();
        }

        float exa = (tid > 0) ? sc_a[tid - 1] : 1.0f;
        float exr = (tid > 0) ? sc_r[tid - 1] : 0.0f;
        float exi = (tid > 0) ? sc_i[tid - 1] : 0.0f;
        float rr = fmaf(exa, carry_r, exr);
        float ri = fmaf(exa, carry_i, exi);
        float ncr = fmaf(sc_a[255], carry_r, sc_r[255]);
        float nci = fmaf(sc_a[255], carry_i, sc_i[255]);

#pragma unroll
        for (int j = 0; j < 8; j++) {
            float a = s_a[j0 + j];
            rr = fmaf(a, rr, s_br[j0 + j]);
            ri = fmaf(a, ri, s_bi[j0 + j]);
            int n = c * CHUNK + j0 + j;
            size_t o = ((size_t)(b * SEQ + n)) * KCH + k;
            g_rr[o] = rr;
            g_ri[o] = ri;
        }
        carry_r = ncr; carry_i = nci;
        __syncthreads();
    }
}

// ---------------- postscan -> rho [hi|lo] bf16 ------------------------------
__device__ __forceinline__ void writeHL(size_t base, int idx, float v) {
    __nv_bfloat16 h, l; bsplit(v, h, l);
    g_rhocat[base + idx]        = h;
    g_rhocat[base + 1024 + idx] = l;
}

__global__ __launch_bounds__(256) void postscan_kernel(const float* __restrict__ lam_ptr) {
    __shared__ float sre[256], simm[256], sgg[256];
    int row = blockIdx.x;
    int k = threadIdx.x;
    size_t o = (size_t)row * KCH + k;

    float rr = g_rr[o], ri = g_ri[o];
    float cs = g_cosb[o], sn = g_sinb[o];
    float be = g_betab[o], gg = g_gb[o];
    float pq = g_pq[o];

    float readout = fmaf(rr, cs, ri * sn);
    rr = fmaf(-be * readout, cs, rr);
    ri = fmaf(-be * readout, sn, ri);

    float mod = sqrtf(fmaf(rr, rr, fmaf(ri, ri, 1e-8f)));
    float scl = fmaxf(mod, 1.0f);
    rr /= scl; ri /= scl;

    float rre = fmaf(rr, cs, ri * sn);
    float rim = fmaf(-rr, sn, ri * cs);

    float rn = sqrtf(fmaf(rre, rre, fmaf(rim, rim, 1e-8f)));
    float ps, pc;
    sincosf(pq, &ps, &pc);
    float align = (rre * pc + rim * ps) / rn;
    float lam = *lam_ptr;
    float gate = 1.0f / (1.0f + expf(-lam * align));
    rre *= gate; rim *= gate;

    sre[k] = rre; simm[k] = rim; sgg[k] = gg;
    __syncthreads();

    size_t ob = (size_t)row * K2;
    writeHL(ob, k, gg * rre);
    writeHL(ob, 256 + k, gg * rim);
    if (k < 255) {
        float are = sre[k], aim = simm[k], bre = sre[k + 1], bim = simm[k + 1];
        float xre = are * bre - aim * bim;
        float xim = are * bim + aim * bre;
        float gc = 0.5f * (sgg[k] + sgg[k + 1]);
        writeHL(ob, 512 + k, gc * xre);
        writeHL(ob, 767 + k, gc * xim);
    } else {
        writeHL(ob, 1022, 0.0f);
        writeHL(ob, 1023, 0.0f);
    }
}

// ---------------- launch ---------------------------------------------------
extern "C" void kernel_launch(void* const* d_in, const int* in_sizes, int n_in,
                              void* d_out, int out_size) {
    const float* x   = (const float*)d_in[0];
    const float* Wp  = (const float*)d_in[1];
    const float* bp  = (const float*)d_in[2];
    const float* Wr  = (const float*)d_in[3];
    const float* Wph = (const float*)d_in[4];
    const float* bph = (const float*)d_in[5];
    const float* lam = (const float*)d_in[6];
    const float* rs  = (const float*)d_in[7];
    float* out = (float*)d_out;

    cudaFuncSetAttribute(mma_gemm, cudaFuncAttributeMaxDynamicSharedMemorySize, GSMEM);

    split_cat_kernel<<<(ROWS * DM / 4 + 255) / 256, 256>>>((const float4*)x,   ROWS * DM / 4, 0);
    split_cat_kernel<<<(NPROJ * DM / 4 + 255) / 256, 256>>>((const float4*)Wp,  NPROJ * DM / 4, 1);
    split_cat_kernel<<<(KCH * DM / 4 + 255) / 256, 256>>>((const float4*)Wph, KCH * DM / 4, 2);
    wres_split_cat_kernel<<<(DM * DM) / 256, 256>>>(Wr);

    // proj = x @ W_proj^T + b_proj   (3-term, 48 virtual k-tiles)
    mma_gemm<<<dim3(NPROJ / TN, ROWS / TM), 256, GSMEM>>>(bp, nullptr, nullptr, NPROJ, NKIT3, 0);
    // phase_query = x @ W_phase^T + b_phase  (single bf16, 16 k-tiles)
    mma_gemm<<<dim3(KCH / TN, ROWS / TM), 256, GSMEM>>>(bph, nullptr, nullptr, KCH, 16, 1);

    prescan_kernel<<<4096, 256>>>();
    scan_kernel<<<BB * KCH, 256>>>();
    postscan_kernel<<<ROWS, 256>>>(lam);

    // out = res_scale * rho @ W_res^T  (3-term, 48 virtual k-tiles)
    mma_gemm<<<dim3(DM / TN, ROWS / TM), 256, GSMEM>>>(nullptr, rs, out, DM, NKIT3, 2);
}